// round 12
// baseline (speedup 1.0000x reference)
#include <cuda_runtime.h>
#include <stdint.h>

#define BSZ   1024
#define NDIM  1024
#define TLEN  100

// d_out layout (float elements)
#define OFF_ACT 0
#define OFF_E3H 2048
#define OFF_E5H (2048 + 102400)
#define OFF_C1H (2048 + 2*102400)
#define OFF_EC3 (2048 + 3*102400)
#define OFF_EC5 (OFF_EC3 + 1048576)
#define OFF_CA1 (OFF_EC5 + 1048576)

__device__ float    g_drive[TLEN * NDIM];
__device__ uint32_t g_keys[2 * TLEN];
__device__ float    g_wt1[NDIM * NDIM];   // wec3ca1^T [n][k], tf32-rounded
__device__ float    g_wt2[NDIM * NDIM];   // wca1ec5^T [n][k], tf32-rounded
__device__ float    g_at1[NDIM * NDIM];   // tf32-rounded ec3 (A of step1)
__device__ float    g_at2[NDIM * NDIM];   // tf32-rounded ca1 (A of step2)
__device__ float    g_part[NDIM * NDIM];  // split-K partial exchange scratch
__device__ int      g_flag[8 * 8 * 2];    // per (m-blk, n-blk, z) ready flags

// GEMM tiling: block 128(M) x 128(N), split-K x2 (K-half 512 = 8 k-tiles of 64).
// 8 warps as 4(m) x 2(n), warp tile 32 x 64. acc[2][8][4] = 64 regs.
#define BM 128
#define BN 128
#define KTILE  64
#define KT_PER 8                                  // k-tiles per K-half
#define PITCH  68                                 // 64 + 4 pad floats
#define STAGE_A_BYTES (BM * PITCH * 4)            // 34816
#define STAGE_BYTES   ((BM + BN) * PITCH * 4)     // 69632
#define NSTAGE 3
#define SMEM_DYN (NSTAGE * STAGE_BYTES)           // 208896

// ---------------------------------------------------------------------------
__device__ __forceinline__ float tf32r(float x) {
    uint32_t u = __float_as_uint(x);
    asm("cvt.rna.tf32.f32 %0, %0;" : "+r"(u));
    return __uint_as_float(u);
}
__device__ __forceinline__ float sigmoidf(float x) { return 1.0f / (1.0f + expf(-x)); }
__device__ __forceinline__ uint32_t smem_to_u32(const void* p) {
    uint32_t a;
    asm("{ .reg .u64 t; cvta.to.shared.u64 t, %1; cvt.u32.u64 %0, t; }" : "=r"(a) : "l"(p));
    return a;
}
__device__ __forceinline__ void cp16(uint32_t dst, const void* src) {
    asm volatile("cp.async.cg.shared.global [%0], [%1], 16;" :: "r"(dst), "l"(src));
}
__device__ __forceinline__ void cp_commit() { asm volatile("cp.async.commit_group;"); }
__device__ __forceinline__ void ldsm4(uint32_t r[4], uint32_t addr) {
    asm volatile("ldmatrix.sync.aligned.m8n8.x4.shared.b16 {%0,%1,%2,%3}, [%4];"
        : "=r"(r[0]), "=r"(r[1]), "=r"(r[2]), "=r"(r[3]) : "r"(addr));
}
__device__ __forceinline__ void mma8(float c[4], const uint32_t a[4], const uint32_t b[2]) {
    asm volatile(
        "mma.sync.aligned.m16n8k8.row.col.f32.tf32.tf32.f32 "
        "{%0,%1,%2,%3}, {%4,%5,%6,%7}, {%8,%9}, {%0,%1,%2,%3};"
        : "+f"(c[0]), "+f"(c[1]), "+f"(c[2]), "+f"(c[3])
        : "r"(a[0]), "r"(a[1]), "r"(a[2]), "r"(a[3]), "r"(b[0]), "r"(b[1]));
}

// ---------------------------------------------------------------------------
// Threefry-2x32 (jax partitionable) — validated
// ---------------------------------------------------------------------------
__device__ __forceinline__ void threefry2x32(uint32_t k0, uint32_t k1,
                                             uint32_t x0, uint32_t x1,
                                             uint32_t& o0, uint32_t& o1) {
    uint32_t ks2 = k0 ^ k1 ^ 0x1BD11BDAu;
    x0 += k0; x1 += k1;
#define TF_R(r) { x0 += x1; x1 = __funnelshift_l(x1, x1, (r)); x1 ^= x0; }
    TF_R(13) TF_R(15) TF_R(26) TF_R(6)
    x0 += k1;  x1 += ks2 + 1u;
    TF_R(17) TF_R(29) TF_R(16) TF_R(24)
    x0 += ks2; x1 += k0 + 2u;
    TF_R(13) TF_R(15) TF_R(26) TF_R(6)
    x0 += k0;  x1 += k1 + 3u;
    TF_R(17) TF_R(29) TF_R(16) TF_R(24)
    x0 += k1;  x1 += ks2 + 4u;
    TF_R(13) TF_R(15) TF_R(26) TF_R(6)
    x0 += ks2; x1 += k0 + 5u;
#undef TF_R
    o0 = x0; o1 = x1;
}

__device__ __forceinline__ bool noise_hit(uint32_t k0, uint32_t k1, uint32_t idx) {
    uint32_t o0, o1;
    threefry2x32(k0, k1, 0u, idx, o0, o1);
    uint32_t bits = o0 ^ o1;
    float u = __uint_as_float((bits >> 9) | 0x3f800000u) - 1.0f;
    return u < 0.004f;
}

// ---------------------------------------------------------------------------
// prep kernel: one-time work in one launch
// ---------------------------------------------------------------------------
__global__ __launch_bounds__(256) void prep_kernel(
    const float* __restrict__ wec3ca1, const float* __restrict__ wca1ec5,
    const float* __restrict__ ec3_last, const float* __restrict__ ec5_last,
    const float* __restrict__ wca3ca1,
    float* __restrict__ ec3, float* __restrict__ ec5)
{
    __shared__ float tile[32][33];
    __shared__ float ca3[NDIM];
    const int blk = blockIdx.x;
    const int tid = threadIdx.x;

    if (blk < 2048) {                        // weight transposes + tf32 round
        const float* W = (blk < 1024) ? wec3ca1 : wca1ec5;
        float* dst     = (blk < 1024) ? g_wt1  : g_wt2;
        int b = blk & 1023;
        int bx = (b & 31) * 32, by = (b >> 5) * 32;
        int x = tid & 31, y = tid >> 5;      // 32 x 8
#pragma unroll
        for (int i = 0; i < 32; i += 8)
            tile[y + i][x] = tf32r(W[(size_t)(by + y + i) * NDIM + bx + x]);
        __syncthreads();
#pragma unroll
        for (int i = 0; i < 32; i += 8)
            dst[(size_t)(bx + y + i) * NDIM + by + x] = tile[x][y + i];
    } else if (blk < 3072) {                 // ec3 init + rounded copy
        int i = ((blk - 2048) * 256 + tid) * 4;
        float4 v = *(const float4*)(ec3_last + i);
        *(float4*)(ec3 + i) = v;
        v.x = tf32r(v.x); v.y = tf32r(v.y); v.z = tf32r(v.z); v.w = tf32r(v.w);
        *(float4*)(g_at1 + i) = v;
    } else if (blk < 4096) {                 // ec5 init
        int i = ((blk - 3072) * 256 + tid) * 4;
        *(float4*)(ec5 + i) = *(const float4*)(ec5_last + i);
    } else if (blk < 4196) {                 // drive rows
        const int t = blk - 4096;
        const float x = (float)t;
        for (int c = tid; c < NDIM; c += 256) {
            float center = (100.0f / 1023.0f) * (float)c;
            float d = center - x;
            ca3[c] = tf32r(expf(-(d * d) / 50.0f));
        }
        __syncthreads();
        for (int n = tid; n < NDIM; n += 256) {
            float acc = 0.0f;
            for (int k = 0; k < NDIM; k++)
                acc += ca3[k] * tf32r(wca3ca1[k * NDIM + n]);
            g_drive[t * NDIM + n] = acc;
        }
    } else {                                 // keys + flag clear
        if (tid < TLEN) {
            uint32_t o0, o1;
            threefry2x32(0u, 42u, 0u, (uint32_t)tid, o0, o1);
            g_keys[2 * tid] = o0; g_keys[2 * tid + 1] = o1;
        }
        if (tid < 128) g_flag[tid] = 0;
    }
}

// ---------------------------------------------------------------------------
// GEMM core: acc[2][8][4] = A[128 x Khalf] @ Bt^T[128 x Khalf], Khalf = 512.
// ---------------------------------------------------------------------------
__device__ __forceinline__ void issue_tile(
    const float* __restrict__ A, const float* __restrict__ Bt,
    int m0, int n0, int kbase, int kt, int stage, uint32_t sb, int tid)
{
#pragma unroll
    for (int i = 0; i < 8; i++) {            // A: 128 rows x 64 floats
        int idx = tid + i * 256;
        int row = idx >> 4, ch = idx & 15;
        cp16(sb + stage * STAGE_BYTES + (uint32_t)(row * PITCH + ch * 4) * 4,
             A + (size_t)(m0 + row) * NDIM + kbase + kt * KTILE + ch * 4);
    }
#pragma unroll
    for (int i = 0; i < 8; i++) {            // B: 128 rows x 64 floats
        int idx = tid + i * 256;
        int row = idx >> 4, ch = idx & 15;
        cp16(sb + stage * STAGE_BYTES + STAGE_A_BYTES + (uint32_t)(row * PITCH + ch * 4) * 4,
             Bt + (size_t)(n0 + row) * NDIM + kbase + kt * KTILE + ch * 4);
    }
    cp_commit();
}

__device__ __forceinline__ void gemm_mma_tf32(
    const float* __restrict__ A, const float* __restrict__ Bt,
    float* sm, float acc[2][8][4], int kbase)
{
    const int tid  = threadIdx.x;
    const int lane = tid & 31, warp = tid >> 5;
    const int wm = warp & 3, wn = warp >> 2;
    const int m0 = blockIdx.y * BM, n0 = blockIdx.x * BN;
    const uint32_t sb = smem_to_u32(sm);

    const int q = lane >> 3, r = lane & 7;
    uint32_t aoff[2], boff[4];
#pragma unroll
    for (int mi = 0; mi < 2; mi++) {
        int rowA = wm * 32 + mi * 16 + r + ((q & 1) ? 8 : 0);
        int colA = (q & 2) ? 4 : 0;
        aoff[mi] = (uint32_t)((rowA * PITCH + colA) * 4);
    }
#pragma unroll
    for (int j = 0; j < 4; j++) {
        int rowB = wn * 64 + j * 16 + r + ((q & 2) ? 8 : 0);
        int colB = (q & 1) ? 4 : 0;
        boff[j] = (uint32_t)(STAGE_A_BYTES + (rowB * PITCH + colB) * 4);
    }

#pragma unroll
    for (int mi = 0; mi < 2; mi++)
#pragma unroll
        for (int nj = 0; nj < 8; nj++)
#pragma unroll
            for (int c = 0; c < 4; c++) acc[mi][nj][c] = 0.0f;

    issue_tile(A, Bt, m0, n0, kbase, 0, 0, sb, tid);
    issue_tile(A, Bt, m0, n0, kbase, 1, 1, sb, tid);

    for (int kt = 0; kt < KT_PER; kt++) {
        if (kt < KT_PER - 2) asm volatile("cp.async.wait_group 1;");
        else                 asm volatile("cp.async.wait_group 0;");
        __syncthreads();
        if (kt + 2 < KT_PER)
            issue_tile(A, Bt, m0, n0, kbase, kt + 2, (kt + 2) % 3, sb, tid);

        const uint32_t st = sb + (uint32_t)(kt % 3) * STAGE_BYTES;
#pragma unroll
        for (int kk = 0; kk < 8; kk++) {
            uint32_t af[2][4], bf[4][4];
            ldsm4(af[0], st + aoff[0] + kk * 32);
            ldsm4(af[1], st + aoff[1] + kk * 32);
#pragma unroll
            for (int j = 0; j < 4; j++)
                ldsm4(bf[j], st + boff[j] + kk * 32);
#pragma unroll
            for (int mi = 0; mi < 2; mi++)
#pragma unroll
                for (int j = 0; j < 4; j++) {
                    mma8(acc[mi][2 * j],     af[mi], &bf[j][0]);
                    mma8(acc[mi][2 * j + 1], af[mi], &bf[j][2]);
                }
        }
    }
}

// ---------------------------------------------------------------------------
// split-K partial exchange. CTA z owns local rows [z*64, z*64+64) (warps with
// wm>>1 == z). Non-owner warps write partials to g_part; flags handshake; owner
// warps combine and run the epilogue. Paired CTAs are guaranteed co-resident
// (128 CTAs, 1/SM, 148 SMs -> single wave).
// ---------------------------------------------------------------------------
__device__ __forceinline__ void splitk_exchange(float acc[2][8][4], bool& warp_owner)
{
    const int lane = threadIdx.x & 31, warp = threadIdx.x >> 5;
    const int group = lane >> 2, tig = lane & 3;
    const int wm = warp & 3, wn = warp >> 2;
    const int m0 = blockIdx.y * BM, n0 = blockIdx.x * BN;
    const int z = blockIdx.z;
    warp_owner = ((wm >> 1) == z);
    const int my_flag   = (blockIdx.y * 8 + blockIdx.x) * 2 + z;
    const int peer_flag = (blockIdx.y * 8 + blockIdx.x) * 2 + (1 - z);

    if (!warp_owner) {
#pragma unroll
        for (int mi = 0; mi < 2; mi++)
#pragma unroll
            for (int nj = 0; nj < 8; nj++)
#pragma unroll
                for (int c = 0; c < 4; c++) {
                    const int m = m0 + wm * 32 + mi * 16 + group + ((c & 2) ? 8 : 0);
                    const int n = n0 + wn * 64 + nj * 8 + tig * 2 + (c & 1);
                    g_part[m * NDIM + n] = acc[mi][nj][c];
                }
    }
    __threadfence();
    __syncthreads();
    if (threadIdx.x == 0) {
        atomicExch(&g_flag[my_flag], 1);                      // release my half
        while (atomicAdd(&g_flag[peer_flag], 0) == 0)         // acquire peer half
            __nanosleep(64);
        atomicExch(&g_flag[peer_flag], 0);                    // reset for next launch
        __threadfence();
    }
    __syncthreads();
    if (warp_owner) {
#pragma unroll
        for (int mi = 0; mi < 2; mi++)
#pragma unroll
            for (int nj = 0; nj < 8; nj++)
#pragma unroll
                for (int c = 0; c < 4; c++) {
                    const int m = m0 + wm * 32 + mi * 16 + group + ((c & 2) ? 8 : 0);
                    const int n = n0 + wn * 64 + nj * 8 + tig * 2 + (c & 1);
                    acc[mi][nj][c] += g_part[m * NDIM + n];
                }
    }
}

// ---------------------------------------------------------------------------
// step1: ca1 = relu(drive_t * (1 + sigmoid(ec3 @ wec3ca1)) - ca1bias)
// ---------------------------------------------------------------------------
__global__ __launch_bounds__(256, 1) void step1_mma(
    const float* __restrict__ ca1bias,
    float* __restrict__ ca1, float* __restrict__ c1h, int t, int last)
{
    extern __shared__ float sm[];
    float acc[2][8][4];
    gemm_mma_tf32(g_at1, g_wt1, sm, acc, blockIdx.z * 512);

    bool owner;
    splitk_exchange(acc, owner);
    if (!owner) return;

    const int lane = threadIdx.x & 31, warp = threadIdx.x >> 5;
    const int group = lane >> 2, tig = lane & 3;
    const int wm = warp & 3, wn = warp >> 2;
    const int m0 = blockIdx.y * BM, n0 = blockIdx.x * BN;
    const float* drive = &g_drive[t * NDIM];

#pragma unroll
    for (int mi = 0; mi < 2; mi++)
#pragma unroll
        for (int nj = 0; nj < 8; nj++)
#pragma unroll
            for (int c = 0; c < 4; c++) {
                const int m = m0 + wm * 32 + mi * 16 + group + ((c & 2) ? 8 : 0);
                const int n = n0 + wn * 64 + nj * 8 + tig * 2 + (c & 1);
                float v = fmaxf(drive[n] * (1.0f + sigmoidf(acc[mi][nj][c])) - ca1bias[n], 0.0f);
                const int gi = m * NDIM + n;
                if (last) ca1[gi] = v;
                g_at2[gi] = tf32r(v);
                if (m == 0) c1h[t * NDIM + n] = v;
            }
}

// ---------------------------------------------------------------------------
// step2: ec5 += ca1 @ wca1ec5; squash; ec3 *= ec5; cue @ t==10; threefry noise
// ---------------------------------------------------------------------------
__global__ __launch_bounds__(256, 1) void step2_mma(
    const int* __restrict__ cue,
    float* __restrict__ ec3, float* __restrict__ ec5,
    float* __restrict__ e3h, float* __restrict__ e5h, int t)
{
    extern __shared__ float sm[];
    float acc[2][8][4];
    gemm_mma_tf32(g_at2, g_wt2, sm, acc, blockIdx.z * 512);

    bool owner;
    splitk_exchange(acc, owner);
    if (!owner) return;

    const int lane = threadIdx.x & 31, warp = threadIdx.x >> 5;
    const int group = lane >> 2, tig = lane & 3;
    const int wm = warp & 3, wn = warp >> 2;
    const int m0 = blockIdx.y * BM, n0 = blockIdx.x * BN;
    const uint32_t k0 = g_keys[2 * t], k1 = g_keys[2 * t + 1];
    const bool at_cue = (t == 10);

#pragma unroll
    for (int mi = 0; mi < 2; mi++)
#pragma unroll
        for (int nj = 0; nj < 8; nj++)
#pragma unroll
            for (int c = 0; c < 4; c++) {
                const int m = m0 + wm * 32 + mi * 16 + group + ((c & 2) ? 8 : 0);
                const int n = n0 + wn * 64 + nj * 8 + tig * 2 + (c & 1);
                const int gi = m * NDIM + n;
                float e5 = ec5[gi] + acc[mi][nj][c];       // 10*TS == 1.0 exactly
                e5 = 0.69f + 0.3f * sigmoidf(4.0f * (e5 - 0.3f));
                float e3 = e5 * ec3[gi];
                if (at_cue && (cue[gi] != 0)) e3 = 0.4f * e3 + 0.6f;
                if (noise_hit(k0, k1, (uint32_t)gi)) e3 = 0.5f * e3 + 0.3f;
                ec5[gi] = e5;
                ec3[gi] = e3;
                g_at1[gi] = tf32r(e3);
                if (m == 0) { e5h[t * NDIM + n] = e5; e3h[t * NDIM + n] = e3; }
            }
}

// ---------------------------------------------------------------------------
// act_cell = ca1 @ wca1act + actbias (tf32 operands, validated)
// ---------------------------------------------------------------------------
__global__ __launch_bounds__(128) void act_kernel(
    const float* __restrict__ ca1, const float* __restrict__ w,
    const float* __restrict__ bias, float* __restrict__ out)
{
    __shared__ float s0[128], s1[128];
    const int b = blockIdx.x;
    float a0 = 0.0f, a1 = 0.0f;
    for (int c = threadIdx.x; c < NDIM; c += 128) {
        float v = tf32r(ca1[b * NDIM + c]);
        a0 += v * tf32r(w[c * 2 + 0]);
        a1 += v * tf32r(w[c * 2 + 1]);
    }
    s0[threadIdx.x] = a0; s1[threadIdx.x] = a1;
    __syncthreads();
    for (int off = 64; off > 0; off >>= 1) {
        if (threadIdx.x < off) {
            s0[threadIdx.x] += s0[threadIdx.x + off];
            s1[threadIdx.x] += s1[threadIdx.x + off];
        }
        __syncthreads();
    }
    if (threadIdx.x == 0) {
        out[b * 2 + 0] = s0[0] + bias[0];
        out[b * 2 + 1] = s1[0] + bias[1];
    }
}

// ---------------------------------------------------------------------------
extern "C" void kernel_launch(void* const* d_in, const int* in_sizes, int n_in,
                              void* d_out, int out_size) {
    const int*   cue      = (const int*)d_in[0];     // bool -> int32 in harness
    const float* ec3_last = (const float*)d_in[1];
    const float* ec5_last = (const float*)d_in[2];
    const float* ca1_last = (const float*)d_in[3];
    const float* ca1bias  = (const float*)d_in[4];
    const float* wca3ca1  = (const float*)d_in[5];
    const float* wec3ca1  = (const float*)d_in[6];
    const float* wca1ec5  = (const float*)d_in[7];
    const float* wca1act  = (const float*)d_in[8];
    const float* actbias  = (const float*)d_in[9];
    (void)ca1_last;

    float* out = (float*)d_out;
    float* act = out + OFF_ACT;
    float* e3h = out + OFF_E3H;
    float* e5h = out + OFF_E5H;
    float* c1h = out + OFF_C1H;
    float* ec3 = out + OFF_EC3;
    float* ec5 = out + OFF_EC5;
    float* ca1 = out + OFF_CA1;

    cudaFuncSetAttribute(step1_mma, cudaFuncAttributeMaxDynamicSharedMemorySize, SMEM_DYN);
    cudaFuncSetAttribute(step2_mma, cudaFuncAttributeMaxDynamicSharedMemorySize, SMEM_DYN);

    prep_kernel<<<4197, 256>>>(wec3ca1, wca1ec5, ec3_last, ec5_last, wca3ca1, ec3, ec5);

    dim3 grid(NDIM / BN, BSZ / BM, 2);     // 8 x 8 x 2 = 128 CTAs, all resident
    for (int t = 0; t < TLEN; t++) {
        step1_mma<<<grid, 256, SMEM_DYN>>>(ca1bias, ca1, c1h, t, t == TLEN - 1);
        step2_mma<<<grid, 256, SMEM_DYN>>>(cue, ec3, ec5, e3h, e5h, t);
    }
    act_kernel<<<BSZ, 128>>>(ca1, wca1act, actbias, act);
}

// round 13
// speedup vs baseline: 1.3952x; 1.3952x over previous
#include <cuda_runtime.h>
#include <stdint.h>

#define BSZ   1024
#define NDIM  1024
#define TLEN  100

// d_out layout (float elements)
#define OFF_ACT 0
#define OFF_E3H 2048
#define OFF_E5H (2048 + 102400)
#define OFF_C1H (2048 + 2*102400)
#define OFF_EC3 (2048 + 3*102400)
#define OFF_EC5 (OFF_EC3 + 1048576)
#define OFF_CA1 (OFF_EC5 + 1048576)

__device__ float    g_drive[TLEN * NDIM];
__device__ uint32_t g_keys[2 * TLEN];
__device__ float    g_wt1[NDIM * NDIM];   // wec3ca1^T [n][k], tf32-rounded
__device__ float    g_wt2[NDIM * NDIM];   // wca1ec5^T [n][k], tf32-rounded
__device__ float    g_at1[NDIM * NDIM];   // tf32-rounded ec3 (A of step1)
__device__ float    g_at2[NDIM * NDIM];   // tf32-rounded ca1 (A of step2)

// GEMM tiling: block 64(M) x 64(N), K-tile 64 (16 iterations), 8 warps 4(m)x2(n),
// warp tile 16 x 32. Grid 16x16 = 256 CTAs -> 2 CTAs/SM (16 warps/SM).
#define BM 64
#define BN 64
#define KTILE  64
#define KTILES 16
#define PITCH  68                                 // 64 + 4 pad floats
#define STAGE_A_BYTES (BM * PITCH * 4)            // 17408
#define STAGE_BYTES   ((BM + BN) * PITCH * 4)     // 34816
#define NSTAGE 3
#define SMEM_DYN (NSTAGE * STAGE_BYTES)           // 104448 -> 2 CTAs/SM

// ---------------------------------------------------------------------------
__device__ __forceinline__ float tf32r(float x) {
    uint32_t u = __float_as_uint(x);
    asm("cvt.rna.tf32.f32 %0, %0;" : "+r"(u));
    return __uint_as_float(u);
}
__device__ __forceinline__ float sigmoidf(float x) { return 1.0f / (1.0f + expf(-x)); }
__device__ __forceinline__ uint32_t smem_to_u32(const void* p) {
    uint32_t a;
    asm("{ .reg .u64 t; cvta.to.shared.u64 t, %1; cvt.u32.u64 %0, t; }" : "=r"(a) : "l"(p));
    return a;
}
__device__ __forceinline__ void cp16(uint32_t dst, const void* src) {
    asm volatile("cp.async.cg.shared.global [%0], [%1], 16;" :: "r"(dst), "l"(src));
}
__device__ __forceinline__ void cp_commit() { asm volatile("cp.async.commit_group;"); }
__device__ __forceinline__ void ldsm4(uint32_t r[4], uint32_t addr) {
    asm volatile("ldmatrix.sync.aligned.m8n8.x4.shared.b16 {%0,%1,%2,%3}, [%4];"
        : "=r"(r[0]), "=r"(r[1]), "=r"(r[2]), "=r"(r[3]) : "r"(addr));
}
__device__ __forceinline__ void mma8(float c[4], const uint32_t a[4], const uint32_t b[2]) {
    asm volatile(
        "mma.sync.aligned.m16n8k8.row.col.f32.tf32.tf32.f32 "
        "{%0,%1,%2,%3}, {%4,%5,%6,%7}, {%8,%9}, {%0,%1,%2,%3};"
        : "+f"(c[0]), "+f"(c[1]), "+f"(c[2]), "+f"(c[3])
        : "r"(a[0]), "r"(a[1]), "r"(a[2]), "r"(a[3]), "r"(b[0]), "r"(b[1]));
}

// ---------------------------------------------------------------------------
// Threefry-2x32 (jax partitionable) — validated
// ---------------------------------------------------------------------------
__device__ __forceinline__ void threefry2x32(uint32_t k0, uint32_t k1,
                                             uint32_t x0, uint32_t x1,
                                             uint32_t& o0, uint32_t& o1) {
    uint32_t ks2 = k0 ^ k1 ^ 0x1BD11BDAu;
    x0 += k0; x1 += k1;
#define TF_R(r) { x0 += x1; x1 = __funnelshift_l(x1, x1, (r)); x1 ^= x0; }
    TF_R(13) TF_R(15) TF_R(26) TF_R(6)
    x0 += k1;  x1 += ks2 + 1u;
    TF_R(17) TF_R(29) TF_R(16) TF_R(24)
    x0 += ks2; x1 += k0 + 2u;
    TF_R(13) TF_R(15) TF_R(26) TF_R(6)
    x0 += k0;  x1 += k1 + 3u;
    TF_R(17) TF_R(29) TF_R(16) TF_R(24)
    x0 += k1;  x1 += ks2 + 4u;
    TF_R(13) TF_R(15) TF_R(26) TF_R(6)
    x0 += ks2; x1 += k0 + 5u;
#undef TF_R
    o0 = x0; o1 = x1;
}

__device__ __forceinline__ bool noise_hit(uint32_t k0, uint32_t k1, uint32_t idx) {
    uint32_t o0, o1;
    threefry2x32(k0, k1, 0u, idx, o0, o1);
    uint32_t bits = o0 ^ o1;
    float u = __uint_as_float((bits >> 9) | 0x3f800000u) - 1.0f;
    return u < 0.004f;
}

// ---------------------------------------------------------------------------
// prep kernel: one-time work in one launch
// ---------------------------------------------------------------------------
__global__ __launch_bounds__(256) void prep_kernel(
    const float* __restrict__ wec3ca1, const float* __restrict__ wca1ec5,
    const float* __restrict__ ec3_last, const float* __restrict__ ec5_last,
    const float* __restrict__ wca3ca1,
    float* __restrict__ ec3, float* __restrict__ ec5)
{
    __shared__ float tile[32][33];
    __shared__ float ca3[NDIM];
    const int blk = blockIdx.x;
    const int tid = threadIdx.x;

    if (blk < 2048) {                        // weight transposes + tf32 round
        const float* W = (blk < 1024) ? wec3ca1 : wca1ec5;
        float* dst     = (blk < 1024) ? g_wt1  : g_wt2;
        int b = blk & 1023;
        int bx = (b & 31) * 32, by = (b >> 5) * 32;
        int x = tid & 31, y = tid >> 5;      // 32 x 8
#pragma unroll
        for (int i = 0; i < 32; i += 8)
            tile[y + i][x] = tf32r(W[(size_t)(by + y + i) * NDIM + bx + x]);
        __syncthreads();
#pragma unroll
        for (int i = 0; i < 32; i += 8)
            dst[(size_t)(bx + y + i) * NDIM + by + x] = tile[x][y + i];
    } else if (blk < 3072) {                 // ec3 init + rounded copy
        int i = ((blk - 2048) * 256 + tid) * 4;
        float4 v = *(const float4*)(ec3_last + i);
        *(float4*)(ec3 + i) = v;
        v.x = tf32r(v.x); v.y = tf32r(v.y); v.z = tf32r(v.z); v.w = tf32r(v.w);
        *(float4*)(g_at1 + i) = v;
    } else if (blk < 4096) {                 // ec5 init
        int i = ((blk - 3072) * 256 + tid) * 4;
        *(float4*)(ec5 + i) = *(const float4*)(ec5_last + i);
    } else if (blk < 4196) {                 // drive rows
        const int t = blk - 4096;
        const float x = (float)t;
        for (int c = tid; c < NDIM; c += 256) {
            float center = (100.0f / 1023.0f) * (float)c;
            float d = center - x;
            ca3[c] = tf32r(expf(-(d * d) / 50.0f));
        }
        __syncthreads();
        for (int n = tid; n < NDIM; n += 256) {
            float acc = 0.0f;
            for (int k = 0; k < NDIM; k++)
                acc += ca3[k] * tf32r(wca3ca1[k * NDIM + n]);
            g_drive[t * NDIM + n] = acc;
        }
    } else {                                 // keys
        if (tid < TLEN) {
            uint32_t o0, o1;
            threefry2x32(0u, 42u, 0u, (uint32_t)tid, o0, o1);
            g_keys[2 * tid] = o0; g_keys[2 * tid + 1] = o1;
        }
    }
}

// ---------------------------------------------------------------------------
// GEMM core: acc[4][4] = A[64 x 1024] @ Bt^T[64 x 1024] tile, warp 16x32.
// ---------------------------------------------------------------------------
__device__ __forceinline__ void issue_tile(
    const float* __restrict__ A, const float* __restrict__ Bt,
    int m0, int n0, int kt, int stage, uint32_t sb, int tid)
{
#pragma unroll
    for (int i = 0; i < 4; i++) {            // A: 64 rows x 64 floats
        int idx = tid + i * 256;
        int row = idx >> 4, ch = idx & 15;
        cp16(sb + stage * STAGE_BYTES + (uint32_t)(row * PITCH + ch * 4) * 4,
             A + (size_t)(m0 + row) * NDIM + kt * KTILE + ch * 4);
    }
#pragma unroll
    for (int i = 0; i < 4; i++) {            // B: 64 rows x 64 floats
        int idx = tid + i * 256;
        int row = idx >> 4, ch = idx & 15;
        cp16(sb + stage * STAGE_BYTES + STAGE_A_BYTES + (uint32_t)(row * PITCH + ch * 4) * 4,
             Bt + (size_t)(n0 + row) * NDIM + kt * KTILE + ch * 4);
    }
    cp_commit();
}

__device__ __forceinline__ void gemm_mma_tf32(
    const float* __restrict__ A, const float* __restrict__ Bt,
    float* sm, float acc[4][4])
{
    const int tid  = threadIdx.x;
    const int lane = tid & 31, warp = tid >> 5;
    const int wm = warp & 3, wn = warp >> 2;
    const int m0 = blockIdx.y * BM, n0 = blockIdx.x * BN;
    const uint32_t sb = smem_to_u32(sm);

    const int q = lane >> 3, r = lane & 7;
    // A fragment (one m16): rows wm*16 .. wm*16+15
    const int rowA = wm * 16 + r + ((q & 1) ? 8 : 0);
    const int colA = (q & 2) ? 4 : 0;
    const uint32_t aoff = (uint32_t)((rowA * PITCH + colA) * 4);
    // B fragments (two n16 -> four n8): rows wn*32 + j*16 ...
    uint32_t boff[2];
#pragma unroll
    for (int j = 0; j < 2; j++) {
        int rowB = wn * 32 + j * 16 + r + ((q & 2) ? 8 : 0);
        int colB = (q & 1) ? 4 : 0;
        boff[j] = (uint32_t)(STAGE_A_BYTES + (rowB * PITCH + colB) * 4);
    }

#pragma unroll
    for (int nj = 0; nj < 4; nj++)
#pragma unroll
        for (int c = 0; c < 4; c++) acc[nj][c] = 0.0f;

    issue_tile(A, Bt, m0, n0, 0, 0, sb, tid);
    issue_tile(A, Bt, m0, n0, 1, 1, sb, tid);

    for (int kt = 0; kt < KTILES; kt++) {
        if (kt < KTILES - 2) asm volatile("cp.async.wait_group 1;");
        else                 asm volatile("cp.async.wait_group 0;");
        __syncthreads();
        if (kt + 2 < KTILES)
            issue_tile(A, Bt, m0, n0, kt + 2, (kt + 2) % 3, sb, tid);

        const uint32_t st = sb + (uint32_t)(kt % 3) * STAGE_BYTES;
#pragma unroll
        for (int kk = 0; kk < 8; kk++) {
            uint32_t af[4], b01[4], b23[4];
            ldsm4(af,  st + aoff    + kk * 32);
            ldsm4(b01, st + boff[0] + kk * 32);
            ldsm4(b23, st + boff[1] + kk * 32);
            mma8(acc[0], af, &b01[0]);
            mma8(acc[1], af, &b01[2]);
            mma8(acc[2], af, &b23[0]);
            mma8(acc[3], af, &b23[2]);
        }
    }
}

// ---------------------------------------------------------------------------
// step1: ca1 = relu(drive_t * (1 + sigmoid(ec3 @ wec3ca1)) - ca1bias)
// ---------------------------------------------------------------------------
__global__ __launch_bounds__(256, 2) void step1_mma(
    const float* __restrict__ ca1bias,
    float* __restrict__ ca1, float* __restrict__ c1h, int t, int last)
{
    extern __shared__ float sm[];
    float acc[4][4];
    gemm_mma_tf32(g_at1, g_wt1, sm, acc);

    const int lane = threadIdx.x & 31, warp = threadIdx.x >> 5;
    const int group = lane >> 2, tig = lane & 3;
    const int wm = warp & 3, wn = warp >> 2;
    const int m0 = blockIdx.y * BM, n0 = blockIdx.x * BN;
    const float* drive = &g_drive[t * NDIM];

#pragma unroll
    for (int nj = 0; nj < 4; nj++)
#pragma unroll
        for (int c = 0; c < 4; c++) {
            const int m = m0 + wm * 16 + group + ((c & 2) ? 8 : 0);
            const int n = n0 + wn * 32 + nj * 8 + tig * 2 + (c & 1);
            float v = fmaxf(drive[n] * (1.0f + sigmoidf(acc[nj][c])) - ca1bias[n], 0.0f);
            const int gi = m * NDIM + n;
            if (last) ca1[gi] = v;
            g_at2[gi] = tf32r(v);
            if (m == 0) c1h[t * NDIM + n] = v;
        }
}

// ---------------------------------------------------------------------------
// step2: ec5 += ca1 @ wca1ec5; squash; ec3 *= ec5; cue @ t==10; threefry noise
// ---------------------------------------------------------------------------
__global__ __launch_bounds__(256, 2) void step2_mma(
    const int* __restrict__ cue,
    float* __restrict__ ec3, float* __restrict__ ec5,
    float* __restrict__ e3h, float* __restrict__ e5h, int t)
{
    extern __shared__ float sm[];
    float acc[4][4];
    gemm_mma_tf32(g_at2, g_wt2, sm, acc);

    const int lane = threadIdx.x & 31, warp = threadIdx.x >> 5;
    const int group = lane >> 2, tig = lane & 3;
    const int wm = warp & 3, wn = warp >> 2;
    const int m0 = blockIdx.y * BM, n0 = blockIdx.x * BN;
    const uint32_t k0 = g_keys[2 * t], k1 = g_keys[2 * t + 1];
    const bool at_cue = (t == 10);

#pragma unroll
    for (int nj = 0; nj < 4; nj++)
#pragma unroll
        for (int c = 0; c < 4; c++) {
            const int m = m0 + wm * 16 + group + ((c & 2) ? 8 : 0);
            const int n = n0 + wn * 32 + nj * 8 + tig * 2 + (c & 1);
            const int gi = m * NDIM + n;
            float e5 = ec5[gi] + acc[nj][c];           // 10*TS == 1.0 exactly
            e5 = 0.69f + 0.3f * sigmoidf(4.0f * (e5 - 0.3f));
            float e3 = e5 * ec3[gi];
            if (at_cue && (cue[gi] != 0)) e3 = 0.4f * e3 + 0.6f;
            if (noise_hit(k0, k1, (uint32_t)gi)) e3 = 0.5f * e3 + 0.3f;
            ec5[gi] = e5;
            ec3[gi] = e3;
            g_at1[gi] = tf32r(e3);
            if (m == 0) { e5h[t * NDIM + n] = e5; e3h[t * NDIM + n] = e3; }
        }
}

// ---------------------------------------------------------------------------
// act_cell = ca1 @ wca1act + actbias (tf32 operands, validated)
// ---------------------------------------------------------------------------
__global__ __launch_bounds__(128) void act_kernel(
    const float* __restrict__ ca1, const float* __restrict__ w,
    const float* __restrict__ bias, float* __restrict__ out)
{
    __shared__ float s0[128], s1[128];
    const int b = blockIdx.x;
    float a0 = 0.0f, a1 = 0.0f;
    for (int c = threadIdx.x; c < NDIM; c += 128) {
        float v = tf32r(ca1[b * NDIM + c]);
        a0 += v * tf32r(w[c * 2 + 0]);
        a1 += v * tf32r(w[c * 2 + 1]);
    }
    s0[threadIdx.x] = a0; s1[threadIdx.x] = a1;
    __syncthreads();
    for (int off = 64; off > 0; off >>= 1) {
        if (threadIdx.x < off) {
            s0[threadIdx.x] += s0[threadIdx.x + off];
            s1[threadIdx.x] += s1[threadIdx.x + off];
        }
        __syncthreads();
    }
    if (threadIdx.x == 0) {
        out[b * 2 + 0] = s0[0] + bias[0];
        out[b * 2 + 1] = s1[0] + bias[1];
    }
}

// ---------------------------------------------------------------------------
extern "C" void kernel_launch(void* const* d_in, const int* in_sizes, int n_in,
                              void* d_out, int out_size) {
    const int*   cue      = (const int*)d_in[0];     // bool -> int32 in harness
    const float* ec3_last = (const float*)d_in[1];
    const float* ec5_last = (const float*)d_in[2];
    const float* ca1_last = (const float*)d_in[3];
    const float* ca1bias  = (const float*)d_in[4];
    const float* wca3ca1  = (const float*)d_in[5];
    const float* wec3ca1  = (const float*)d_in[6];
    const float* wca1ec5  = (const float*)d_in[7];
    const float* wca1act  = (const float*)d_in[8];
    const float* actbias  = (const float*)d_in[9];
    (void)ca1_last;

    float* out = (float*)d_out;
    float* act = out + OFF_ACT;
    float* e3h = out + OFF_E3H;
    float* e5h = out + OFF_E5H;
    float* c1h = out + OFF_C1H;
    float* ec3 = out + OFF_EC3;
    float* ec5 = out + OFF_EC5;
    float* ca1 = out + OFF_CA1;

    cudaFuncSetAttribute(step1_mma, cudaFuncAttributeMaxDynamicSharedMemorySize, SMEM_DYN);
    cudaFuncSetAttribute(step2_mma, cudaFuncAttributeMaxDynamicSharedMemorySize, SMEM_DYN);

    prep_kernel<<<4197, 256>>>(wec3ca1, wca1ec5, ec3_last, ec5_last, wca3ca1, ec3, ec5);

    dim3 grid(NDIM / BN, BSZ / BM);        // 16 x 16 = 256 CTAs -> 2/SM
    for (int t = 0; t < TLEN; t++) {
        step1_mma<<<grid, 256, SMEM_DYN>>>(ca1bias, ca1, c1h, t, t == TLEN - 1);
        step2_mma<<<grid, 256, SMEM_DYN>>>(cue, ec3, ec5, e3h, e5h, t);
    }
    act_kernel<<<BSZ, 128>>>(ca1, wca1act, actbias, act);
}

// round 14
// speedup vs baseline: 2.1084x; 1.5112x over previous
#include <cuda_runtime.h>
#include <cuda_fp16.h>
#include <stdint.h>

#define BSZ   1024
#define NDIM  1024
#define TLEN  100

// d_out layout (float elements)
#define OFF_ACT 0
#define OFF_E3H 2048
#define OFF_E5H (2048 + 102400)
#define OFF_C1H (2048 + 2*102400)
#define OFF_EC3 (2048 + 3*102400)
#define OFF_EC5 (OFF_EC3 + 1048576)
#define OFF_CA1 (OFF_EC5 + 1048576)

__device__ float    g_drive[TLEN * NDIM];
__device__ uint32_t g_keys[2 * TLEN];
__device__ __half   g_wt1[NDIM * NDIM];   // wec3ca1^T [n][k], fp16
__device__ __half   g_wt2[NDIM * NDIM];   // wca1ec5^T [n][k], fp16
__device__ __half   g_at1[NDIM * NDIM];   // fp16 ec3 (A of step1)
__device__ __half   g_at2[NDIM * NDIM];   // fp16 ca1 (A of step2)

// GEMM tiling: block 128(M) x 64(N), K-tile 128 halves (8 iterations),
// 8 warps 4(m)x2(n), warp tile 32x32, fp16 m16n8k16 mma (fp32 accum).
// Smem byte layout identical to the validated tf32 config (PITCH 68 u32).
#define KTILE_H 128
#define KTILES  8
#define PITCH   68                                // u32 units per row (272 B)
#define STAGE_A_BYTES (128 * PITCH * 4)           // 34816
#define STAGE_BYTES   (192 * PITCH * 4)           // 52224
#define NSTAGE 3
#define SMEM_DYN (NSTAGE * STAGE_BYTES)           // 156672

// ---------------------------------------------------------------------------
__device__ __forceinline__ float tf32r(float x) {
    uint32_t u = __float_as_uint(x);
    asm("cvt.rna.tf32.f32 %0, %0;" : "+r"(u));
    return __uint_as_float(u);
}
__device__ __forceinline__ float sigmoidf(float x) { return 1.0f / (1.0f + expf(-x)); }
__device__ __forceinline__ uint32_t smem_to_u32(const void* p) {
    uint32_t a;
    asm("{ .reg .u64 t; cvta.to.shared.u64 t, %1; cvt.u32.u64 %0, t; }" : "=r"(a) : "l"(p));
    return a;
}
__device__ __forceinline__ void cp16(uint32_t dst, const void* src) {
    asm volatile("cp.async.cg.shared.global [%0], [%1], 16;" :: "r"(dst), "l"(src));
}
__device__ __forceinline__ void cp_commit() { asm volatile("cp.async.commit_group;"); }
__device__ __forceinline__ void ldsm4(uint32_t r[4], uint32_t addr) {
    asm volatile("ldmatrix.sync.aligned.m8n8.x4.shared.b16 {%0,%1,%2,%3}, [%4];"
        : "=r"(r[0]), "=r"(r[1]), "=r"(r[2]), "=r"(r[3]) : "r"(addr));
}
// fp16 m16n8k16: 4 a-regs, 2 b-regs, fp32 accumulate
__device__ __forceinline__ void mma16(float c[4], const uint32_t a[4],
                                      uint32_t b0, uint32_t b1) {
    asm volatile(
        "mma.sync.aligned.m16n8k16.row.col.f32.f16.f16.f32 "
        "{%0,%1,%2,%3}, {%4,%5,%6,%7}, {%8,%9}, {%0,%1,%2,%3};"
        : "+f"(c[0]), "+f"(c[1]), "+f"(c[2]), "+f"(c[3])
        : "r"(a[0]), "r"(a[1]), "r"(a[2]), "r"(a[3]), "r"(b0), "r"(b1));
}

// ---------------------------------------------------------------------------
// Threefry-2x32 (jax partitionable) — validated
// ---------------------------------------------------------------------------
__device__ __forceinline__ void threefry2x32(uint32_t k0, uint32_t k1,
                                             uint32_t x0, uint32_t x1,
                                             uint32_t& o0, uint32_t& o1) {
    uint32_t ks2 = k0 ^ k1 ^ 0x1BD11BDAu;
    x0 += k0; x1 += k1;
#define TF_R(r) { x0 += x1; x1 = __funnelshift_l(x1, x1, (r)); x1 ^= x0; }
    TF_R(13) TF_R(15) TF_R(26) TF_R(6)
    x0 += k1;  x1 += ks2 + 1u;
    TF_R(17) TF_R(29) TF_R(16) TF_R(24)
    x0 += ks2; x1 += k0 + 2u;
    TF_R(13) TF_R(15) TF_R(26) TF_R(6)
    x0 += k0;  x1 += k1 + 3u;
    TF_R(17) TF_R(29) TF_R(16) TF_R(24)
    x0 += k1;  x1 += ks2 + 4u;
    TF_R(13) TF_R(15) TF_R(26) TF_R(6)
    x0 += ks2; x1 += k0 + 5u;
#undef TF_R
    o0 = x0; o1 = x1;
}

__device__ __forceinline__ bool noise_hit(uint32_t k0, uint32_t k1, uint32_t idx) {
    uint32_t o0, o1;
    threefry2x32(k0, k1, 0u, idx, o0, o1);
    uint32_t bits = o0 ^ o1;
    float u = __uint_as_float((bits >> 9) | 0x3f800000u) - 1.0f;
    return u < 0.004f;
}

// ---------------------------------------------------------------------------
// prep kernel: one-time work in one launch
// ---------------------------------------------------------------------------
__global__ __launch_bounds__(256) void prep_kernel(
    const float* __restrict__ wec3ca1, const float* __restrict__ wca1ec5,
    const float* __restrict__ ec3_last, const float* __restrict__ ec5_last,
    const float* __restrict__ wca3ca1,
    float* __restrict__ ec3, float* __restrict__ ec5)
{
    __shared__ float tile[32][33];
    __shared__ float ca3[NDIM];
    const int blk = blockIdx.x;
    const int tid = threadIdx.x;

    if (blk < 2048) {                        // weight transposes -> fp16
        const float* W = (blk < 1024) ? wec3ca1 : wca1ec5;
        __half* dst    = (blk < 1024) ? g_wt1  : g_wt2;
        int b = blk & 1023;
        int bx = (b & 31) * 32, by = (b >> 5) * 32;
        int x = tid & 31, y = tid >> 5;      // 32 x 8
#pragma unroll
        for (int i = 0; i < 32; i += 8)
            tile[y + i][x] = W[(size_t)(by + y + i) * NDIM + bx + x];
        __syncthreads();
#pragma unroll
        for (int i = 0; i < 32; i += 8)
            dst[(size_t)(bx + y + i) * NDIM + by + x] = __float2half(tile[x][y + i]);
    } else if (blk < 3072) {                 // ec3 init + fp16 copy
        int i = ((blk - 2048) * 256 + tid) * 4;
        float4 v = *(const float4*)(ec3_last + i);
        *(float4*)(ec3 + i) = v;
        g_at1[i + 0] = __float2half(v.x);
        g_at1[i + 1] = __float2half(v.y);
        g_at1[i + 2] = __float2half(v.z);
        g_at1[i + 3] = __float2half(v.w);
    } else if (blk < 4096) {                 // ec5 init
        int i = ((blk - 3072) * 256 + tid) * 4;
        *(float4*)(ec5 + i) = *(const float4*)(ec5_last + i);
    } else if (blk < 4196) {                 // drive rows (tf32-emulated fp32)
        const int t = blk - 4096;
        const float x = (float)t;
        for (int c = tid; c < NDIM; c += 256) {
            float center = (100.0f / 1023.0f) * (float)c;
            float d = center - x;
            ca3[c] = tf32r(expf(-(d * d) / 50.0f));
        }
        __syncthreads();
        for (int n = tid; n < NDIM; n += 256) {
            float acc = 0.0f;
            for (int k = 0; k < NDIM; k++)
                acc += ca3[k] * tf32r(wca3ca1[k * NDIM + n]);
            g_drive[t * NDIM + n] = acc;
        }
    } else {                                 // keys
        if (tid < TLEN) {
            uint32_t o0, o1;
            threefry2x32(0u, 42u, 0u, (uint32_t)tid, o0, o1);
            g_keys[2 * tid] = o0; g_keys[2 * tid + 1] = o1;
        }
    }
}

// ---------------------------------------------------------------------------
// fp16 GEMM core: acc[2][4][4] = A[128 x 1024] @ Bt^T, block 128x64, K-tile 128.
// ---------------------------------------------------------------------------
__device__ __forceinline__ void issue_tile(
    const __half* __restrict__ A, const __half* __restrict__ Bt,
    int m0, int n0, int kt, int stage, uint32_t sb, int tid)
{
#pragma unroll
    for (int i = 0; i < 8; i++) {            // A: 128 rows x 128 halves (16 chunks)
        int idx = tid + i * 256;
        int row = idx >> 4, ch = idx & 15;
        cp16(sb + stage * STAGE_BYTES + (uint32_t)(row * PITCH + ch * 4) * 4,
             A + (size_t)(m0 + row) * NDIM + kt * KTILE_H + ch * 8);
    }
#pragma unroll
    for (int i = 0; i < 4; i++) {            // B: 64 rows x 128 halves
        int idx = tid + i * 256;
        int row = idx >> 4, ch = idx & 15;
        cp16(sb + stage * STAGE_BYTES + STAGE_A_BYTES + (uint32_t)(row * PITCH + ch * 4) * 4,
             Bt + (size_t)(n0 + row) * NDIM + kt * KTILE_H + ch * 8);
    }
    cp_commit();
}

__device__ __forceinline__ void gemm_mma_fp16(
    const __half* __restrict__ A, const __half* __restrict__ Bt,
    float* sm, float acc[2][4][4])
{
    const int tid  = threadIdx.x;
    const int lane = tid & 31, warp = tid >> 5;
    const int wm = warp & 3, wn = warp >> 2;
    const int m0 = blockIdx.y * 128, n0 = blockIdx.x * 64;
    const uint32_t sb = smem_to_u32(sm);

    const int q = lane >> 3, r = lane & 7;
    // A fragments: (q&1)->m+8, (q&2)->k+8 (4 u32). Same structure as validated tf32 path.
    uint32_t aoff[2];
#pragma unroll
    for (int mi = 0; mi < 2; mi++) {
        int rowA = wm * 32 + mi * 16 + r + ((q & 1) ? 8 : 0);
        int colA = (q & 2) ? 4 : 0;
        aoff[mi] = (uint32_t)((rowA * PITCH + colA) * 4);
    }
    // B fragments: (q&2)->n+8, (q&1)->k+8. frag n0-7 = {r0,r1}, n8-15 = {r2,r3}.
    uint32_t boff[2];
#pragma unroll
    for (int j = 0; j < 2; j++) {
        int rowB = wn * 32 + j * 16 + r + ((q & 2) ? 8 : 0);
        int colB = (q & 1) ? 4 : 0;
        boff[j] = (uint32_t)(STAGE_A_BYTES + (rowB * PITCH + colB) * 4);
    }

#pragma unroll
    for (int mi = 0; mi < 2; mi++)
#pragma unroll
        for (int nj = 0; nj < 4; nj++)
#pragma unroll
            for (int c = 0; c < 4; c++) acc[mi][nj][c] = 0.0f;

    issue_tile(A, Bt, m0, n0, 0, 0, sb, tid);
    issue_tile(A, Bt, m0, n0, 1, 1, sb, tid);

    for (int kt = 0; kt < KTILES; kt++) {
        if (kt < KTILES - 2) asm volatile("cp.async.wait_group 1;");
        else                 asm volatile("cp.async.wait_group 0;");
        __syncthreads();

        const uint32_t st = sb + (uint32_t)(kt % 3) * STAGE_BYTES;
#pragma unroll
        for (int kk = 0; kk < 8; kk++) {       // 8 k16-groups per 128-K tile
            uint32_t af[2][4], b01[4], b23[4];
            ldsm4(af[0], st + aoff[0] + kk * 32);
            ldsm4(af[1], st + aoff[1] + kk * 32);
            ldsm4(b01,   st + boff[0] + kk * 32);
            ldsm4(b23,   st + boff[1] + kk * 32);
#pragma unroll
            for (int mi = 0; mi < 2; mi++) {
                mma16(acc[mi][0], af[mi], b01[0], b01[1]);
                mma16(acc[mi][1], af[mi], b01[2], b01[3]);
                mma16(acc[mi][2], af[mi], b23[0], b23[1]);
                mma16(acc[mi][3], af[mi], b23[2], b23[3]);
            }
        }
        if (kt + 2 < KTILES)
            issue_tile(A, Bt, m0, n0, kt + 2, (kt + 2) % 3, sb, tid);
    }
}

// ---------------------------------------------------------------------------
// step1: ca1 = relu(drive_t * (1 + sigmoid(ec3 @ wec3ca1)) - ca1bias)
// ---------------------------------------------------------------------------
__global__ __launch_bounds__(256) void step1_mma(
    const float* __restrict__ ca1bias,
    float* __restrict__ ca1, float* __restrict__ c1h, int t, int last)
{
    extern __shared__ float sm[];
    float acc[2][4][4];
    gemm_mma_fp16(g_at1, g_wt1, sm, acc);

    const int lane = threadIdx.x & 31, warp = threadIdx.x >> 5;
    const int group = lane >> 2, tig = lane & 3;
    const int wm = warp & 3, wn = warp >> 2;
    const int m0 = blockIdx.y * 128, n0 = blockIdx.x * 64;
    const float* drive = &g_drive[t * NDIM];

#pragma unroll
    for (int mi = 0; mi < 2; mi++)
#pragma unroll
        for (int nj = 0; nj < 4; nj++)
#pragma unroll
            for (int c = 0; c < 4; c++) {
                const int m = m0 + wm * 32 + mi * 16 + group + ((c & 2) ? 8 : 0);
                const int n = n0 + wn * 32 + nj * 8 + tig * 2 + (c & 1);
                float v = fmaxf(drive[n] * (1.0f + sigmoidf(acc[mi][nj][c])) - ca1bias[n], 0.0f);
                const int gi = m * NDIM + n;
                if (last) ca1[gi] = v;
                g_at2[gi] = __float2half(v);
                if (m == 0) c1h[t * NDIM + n] = v;
            }
}

// ---------------------------------------------------------------------------
// step2: ec5 += ca1 @ wca1ec5; squash; ec3 *= ec5; cue @ t==10; threefry noise
// ---------------------------------------------------------------------------
__global__ __launch_bounds__(256) void step2_mma(
    const int* __restrict__ cue,
    float* __restrict__ ec3, float* __restrict__ ec5,
    float* __restrict__ e3h, float* __restrict__ e5h, int t)
{
    extern __shared__ float sm[];
    float acc[2][4][4];
    gemm_mma_fp16(g_at2, g_wt2, sm, acc);

    const int lane = threadIdx.x & 31, warp = threadIdx.x >> 5;
    const int group = lane >> 2, tig = lane & 3;
    const int wm = warp & 3, wn = warp >> 2;
    const int m0 = blockIdx.y * 128, n0 = blockIdx.x * 64;
    const uint32_t k0 = g_keys[2 * t], k1 = g_keys[2 * t + 1];
    const bool at_cue = (t == 10);

#pragma unroll
    for (int mi = 0; mi < 2; mi++)
#pragma unroll
        for (int nj = 0; nj < 4; nj++)
#pragma unroll
            for (int c = 0; c < 4; c++) {
                const int m = m0 + wm * 32 + mi * 16 + group + ((c & 2) ? 8 : 0);
                const int n = n0 + wn * 32 + nj * 8 + tig * 2 + (c & 1);
                const int gi = m * NDIM + n;
                float e5 = ec5[gi] + acc[mi][nj][c];       // 10*TS == 1.0 exactly
                e5 = 0.69f + 0.3f * sigmoidf(4.0f * (e5 - 0.3f));
                float e3 = e5 * ec3[gi];
                if (at_cue && (cue[gi] != 0)) e3 = 0.4f * e3 + 0.6f;
                if (noise_hit(k0, k1, (uint32_t)gi)) e3 = 0.5f * e3 + 0.3f;
                ec5[gi] = e5;
                ec3[gi] = e3;
                g_at1[gi] = __float2half(e3);
                if (m == 0) { e5h[t * NDIM + n] = e5; e3h[t * NDIM + n] = e3; }
            }
}

// ---------------------------------------------------------------------------
// act_cell = ca1 @ wca1act + actbias (tf32 operands, validated)
// ---------------------------------------------------------------------------
__global__ __launch_bounds__(128) void act_kernel(
    const float* __restrict__ ca1, const float* __restrict__ w,
    const float* __restrict__ bias, float* __restrict__ out)
{
    __shared__ float s0[128], s1[128];
    const int b = blockIdx.x;
    float a0 = 0.0f, a1 = 0.0f;
    for (int c = threadIdx.x; c < NDIM; c += 128) {
        float v = tf32r(ca1[b * NDIM + c]);
        a0 += v * tf32r(w[c * 2 + 0]);
        a1 += v * tf32r(w[c * 2 + 1]);
    }
    s0[threadIdx.x] = a0; s1[threadIdx.x] = a1;
    __syncthreads();
    for (int off = 64; off > 0; off >>= 1) {
        if (threadIdx.x < off) {
            s0[threadIdx.x] += s0[threadIdx.x + off];
            s1[threadIdx.x] += s1[threadIdx.x + off];
        }
        __syncthreads();
    }
    if (threadIdx.x == 0) {
        out[b * 2 + 0] = s0[0] + bias[0];
        out[b * 2 + 1] = s1[0] + bias[1];
    }
}

// ---------------------------------------------------------------------------
extern "C" void kernel_launch(void* const* d_in, const int* in_sizes, int n_in,
                              void* d_out, int out_size) {
    const int*   cue      = (const int*)d_in[0];     // bool -> int32 in harness
    const float* ec3_last = (const float*)d_in[1];
    const float* ec5_last = (const float*)d_in[2];
    const float* ca1_last = (const float*)d_in[3];
    const float* ca1bias  = (const float*)d_in[4];
    const float* wca3ca1  = (const float*)d_in[5];
    const float* wec3ca1  = (const float*)d_in[6];
    const float* wca1ec5  = (const float*)d_in[7];
    const float* wca1act  = (const float*)d_in[8];
    const float* actbias  = (const float*)d_in[9];
    (void)ca1_last;

    float* out = (float*)d_out;
    float* act = out + OFF_ACT;
    float* e3h = out + OFF_E3H;
    float* e5h = out + OFF_E5H;
    float* c1h = out + OFF_C1H;
    float* ec3 = out + OFF_EC3;
    float* ec5 = out + OFF_EC5;
    float* ca1 = out + OFF_CA1;

    cudaFuncSetAttribute(step1_mma, cudaFuncAttributeMaxDynamicSharedMemorySize, SMEM_DYN);
    cudaFuncSetAttribute(step2_mma, cudaFuncAttributeMaxDynamicSharedMemorySize, SMEM_DYN);

    prep_kernel<<<4197, 256>>>(wec3ca1, wca1ec5, ec3_last, ec5_last, wca3ca1, ec3, ec5);

    dim3 grid(NDIM / 64, BSZ / 128);       // 16 x 8 = 128 CTAs
    for (int t = 0; t < TLEN; t++) {
        step1_mma<<<grid, 256, SMEM_DYN>>>(ca1bias, ca1, c1h, t, t == TLEN - 1);
        step2_mma<<<grid, 256, SMEM_DYN>>>(cue, ec3, ec5, e3h, e5h, t);
    }
    act_kernel<<<BSZ, 128>>>(ca1, wca1act, actbias, act);
}

// round 15
// speedup vs baseline: 2.4470x; 1.1606x over previous
#include <cuda_runtime.h>
#include <cuda_fp16.h>
#include <stdint.h>

#define BSZ   1024
#define NDIM  1024
#define TLEN  100

// d_out layout (float elements)
#define OFF_ACT 0
#define OFF_E3H 2048
#define OFF_E5H (2048 + 102400)
#define OFF_C1H (2048 + 2*102400)
#define OFF_EC3 (2048 + 3*102400)
#define OFF_EC5 (OFF_EC3 + 1048576)
#define OFF_CA1 (OFF_EC5 + 1048576)

// Activations/weights live in k-tile-major swizzled fp16 layout:
//   idx(row, col) = kt*131072 + row*128 + ((chunk ^ (row&7))<<3) + (col&7)
//   kt = col>>7, chunk = (col&127)>>3     (128 halves = 256 B per row per kt)
__device__ float    g_drive[TLEN * NDIM];
__device__ uint32_t g_keys[2 * TLEN];
__device__ __half   g_wt1[NDIM * NDIM];   // wec3ca1^T swizzled tile-major
__device__ __half   g_wt2[NDIM * NDIM];   // wca1ec5^T swizzled tile-major
__device__ __half   g_at1[NDIM * NDIM];   // ec3 (A of step1) swizzled tile-major
__device__ __half   g_at2[NDIM * NDIM];   // ca1 (A of step2) swizzled tile-major

#define KTILES  8
#define SLAB    131072                            // halves per k-tile slab (1024*128)
#define A_BYTES 32768                             // 128 rows * 256B
#define B_BYTES 16384                             // 64 rows * 256B
#define STAGE_BYTES (A_BYTES + B_BYTES)           // 49152
#define NSTAGE 3
#define SM_BAR  (NSTAGE * STAGE_BYTES)            // 147456
#define SMEM_DYN (SM_BAR + 64)

__device__ __forceinline__ size_t sw_idx(int row, int col) {
    int kt = col >> 7, c = (col & 127) >> 3, w = col & 7;
    return (size_t)kt * SLAB + (size_t)row * 128 + (size_t)(((c ^ (row & 7)) << 3) + w);
}

// ---------------------------------------------------------------------------
__device__ __forceinline__ float tf32r(float x) {
    uint32_t u = __float_as_uint(x);
    asm("cvt.rna.tf32.f32 %0, %0;" : "+r"(u));
    return __uint_as_float(u);
}
__device__ __forceinline__ float sigmoidf(float x) { return 1.0f / (1.0f + expf(-x)); }
__device__ __forceinline__ uint32_t smem_to_u32(const void* p) {
    uint32_t a;
    asm("{ .reg .u64 t; cvta.to.shared.u64 t, %1; cvt.u32.u64 %0, t; }" : "=r"(a) : "l"(p));
    return a;
}
#define MBARRIER_INIT(mbar, count) \
    asm volatile("mbarrier.init.shared.b64 [%0], %1;" :: "r"((uint32_t)(mbar)), "r"((uint32_t)(count)) : "memory")
#define MBARRIER_EXPECT_TX(mbar, bytes) \
    asm volatile("mbarrier.arrive.expect_tx.shared.b64 _, [%0], %1;" :: "r"((uint32_t)(mbar)), "r"((uint32_t)(bytes)) : "memory")
#define MBARRIER_WAIT_PARITY(mbar, parity) do { \
    uint32_t _m = (uint32_t)(mbar), _p = (uint32_t)(parity), _d; \
    asm volatile("{\n\t.reg .pred p;\n\t" \
        "mbarrier.try_wait.parity.acquire.cta.shared::cta.b64 p, [%1], %2;\n\t" \
        "selp.b32 %0, 1, 0, p;\n\t}" : "=r"(_d) : "r"(_m), "r"(_p) : "memory"); \
    if (!_d) { \
        asm volatile("{\n\t.reg .pred P1;\n\t" \
            "WL_%=:\n\t" \
            "mbarrier.try_wait.parity.acquire.cta.shared::cta.b64 P1, [%0], %1, 0x989680;\n\t" \
            "@P1 bra.uni WD_%=;\n\t" \
            "bra.uni WL_%=;\n\t" \
            "WD_%=:\n\t}" :: "r"(_m), "r"(_p) : "memory"); \
    } \
} while (0)
__device__ __forceinline__ void bulk_g2s(uint32_t dst, const void* src, uint32_t bytes, uint32_t mbar) {
    asm volatile("cp.async.bulk.shared::cta.global.mbarrier::complete_tx::bytes [%0], [%1], %2, [%3];"
        :: "r"(dst), "l"(src), "r"(bytes), "r"(mbar) : "memory");
}
__device__ __forceinline__ void ldsm4(uint32_t r[4], uint32_t addr) {
    asm volatile("ldmatrix.sync.aligned.m8n8.x4.shared.b16 {%0,%1,%2,%3}, [%4];"
        : "=r"(r[0]), "=r"(r[1]), "=r"(r[2]), "=r"(r[3]) : "r"(addr));
}
__device__ __forceinline__ void mma16(float c[4], const uint32_t a[4],
                                      uint32_t b0, uint32_t b1) {
    asm volatile(
        "mma.sync.aligned.m16n8k16.row.col.f32.f16.f16.f32 "
        "{%0,%1,%2,%3}, {%4,%5,%6,%7}, {%8,%9}, {%0,%1,%2,%3};"
        : "+f"(c[0]), "+f"(c[1]), "+f"(c[2]), "+f"(c[3])
        : "r"(a[0]), "r"(a[1]), "r"(a[2]), "r"(a[3]), "r"(b0), "r"(b1));
}

// ---------------------------------------------------------------------------
// Threefry-2x32 (jax partitionable) — validated
// ---------------------------------------------------------------------------
__device__ __forceinline__ void threefry2x32(uint32_t k0, uint32_t k1,
                                             uint32_t x0, uint32_t x1,
                                             uint32_t& o0, uint32_t& o1) {
    uint32_t ks2 = k0 ^ k1 ^ 0x1BD11BDAu;
    x0 += k0; x1 += k1;
#define TF_R(r) { x0 += x1; x1 = __funnelshift_l(x1, x1, (r)); x1 ^= x0; }
    TF_R(13) TF_R(15) TF_R(26) TF_R(6)
    x0 += k1;  x1 += ks2 + 1u;
    TF_R(17) TF_R(29) TF_R(16) TF_R(24)
    x0 += ks2; x1 += k0 + 2u;
    TF_R(13) TF_R(15) TF_R(26) TF_R(6)
    x0 += k0;  x1 += k1 + 3u;
    TF_R(17) TF_R(29) TF_R(16) TF_R(24)
    x0 += k1;  x1 += ks2 + 4u;
    TF_R(13) TF_R(15) TF_R(26) TF_R(6)
    x0 += ks2; x1 += k0 + 5u;
#undef TF_R
    o0 = x0; o1 = x1;
}

__device__ __forceinline__ bool noise_hit(uint32_t k0, uint32_t k1, uint32_t idx) {
    uint32_t o0, o1;
    threefry2x32(k0, k1, 0u, idx, o0, o1);
    uint32_t bits = o0 ^ o1;
    float u = __uint_as_float((bits >> 9) | 0x3f800000u) - 1.0f;
    return u < 0.004f;
}

// ---------------------------------------------------------------------------
// prep kernel: one-time work in one launch
// ---------------------------------------------------------------------------
__global__ __launch_bounds__(256) void prep_kernel(
    const float* __restrict__ wec3ca1, const float* __restrict__ wca1ec5,
    const float* __restrict__ ec3_last, const float* __restrict__ ec5_last,
    const float* __restrict__ wca3ca1,
    float* __restrict__ ec3, float* __restrict__ ec5)
{
    __shared__ float tile[32][33];
    __shared__ float ca3[NDIM];
    const int blk = blockIdx.x;
    const int tid = threadIdx.x;

    if (blk < 2048) {                        // weight transposes -> swizzled fp16
        const float* W = (blk < 1024) ? wec3ca1 : wca1ec5;
        __half* dst    = (blk < 1024) ? g_wt1  : g_wt2;
        int b = blk & 1023;
        int bx = (b & 31) * 32, by = (b >> 5) * 32;
        int x = tid & 31, y = tid >> 5;      // 32 x 8
#pragma unroll
        for (int i = 0; i < 32; i += 8)
            tile[y + i][x] = W[(size_t)(by + y + i) * NDIM + bx + x];
        __syncthreads();
#pragma unroll
        for (int i = 0; i < 32; i += 8) {
            int n = bx + y + i, k = by + x;  // row of Wt = n, col = k
            dst[sw_idx(n, k)] = __float2half(tile[x][y + i]);
        }
    } else if (blk < 3072) {                 // ec3 init + swizzled fp16 copy
        int i = ((blk - 2048) * 256 + tid) * 4;
        int m = i >> 10, n = i & 1023;
        float4 v = *(const float4*)(ec3_last + i);
        *(float4*)(ec3 + i) = v;
        g_at1[sw_idx(m, n + 0)] = __float2half(v.x);
        g_at1[sw_idx(m, n + 1)] = __float2half(v.y);
        g_at1[sw_idx(m, n + 2)] = __float2half(v.z);
        g_at1[sw_idx(m, n + 3)] = __float2half(v.w);
    } else if (blk < 4096) {                 // ec5 init
        int i = ((blk - 3072) * 256 + tid) * 4;
        *(float4*)(ec5 + i) = *(const float4*)(ec5_last + i);
    } else if (blk < 4196) {                 // drive rows (tf32-emulated fp32)
        const int t = blk - 4096;
        const float x = (float)t;
        for (int c = tid; c < NDIM; c += 256) {
            float center = (100.0f / 1023.0f) * (float)c;
            float d = center - x;
            ca3[c] = tf32r(expf(-(d * d) / 50.0f));
        }
        __syncthreads();
        for (int n = tid; n < NDIM; n += 256) {
            float acc = 0.0f;
            for (int k = 0; k < NDIM; k++)
                acc += ca3[k] * tf32r(wca3ca1[k * NDIM + n]);
            g_drive[t * NDIM + n] = acc;
        }
    } else {                                 // keys
        if (tid < TLEN) {
            uint32_t o0, o1;
            threefry2x32(0u, 42u, 0u, (uint32_t)tid, o0, o1);
            g_keys[2 * tid] = o0; g_keys[2 * tid + 1] = o1;
        }
    }
}

// ---------------------------------------------------------------------------
// fp16 GEMM core with TMA bulk loads: acc[2][4][4], block 128x64, 8 k-tiles.
// ---------------------------------------------------------------------------
__device__ __forceinline__ void gemm_mma_fp16(
    const __half* __restrict__ A, const __half* __restrict__ Bt,
    char* smp, float acc[2][4][4])
{
    const int tid  = threadIdx.x;
    const int lane = tid & 31, warp = tid >> 5;
    const int wm = warp & 3, wn = warp >> 2;
    const int m0 = blockIdx.y * 128, n0 = blockIdx.x * 64;
    const uint32_t sb = smem_to_u32(smp);
    const uint32_t bar = sb + SM_BAR;

    if (tid == 0) {
        MBARRIER_INIT(bar + 0, 1);
        MBARRIER_INIT(bar + 8, 1);
        MBARRIER_INIT(bar + 16, 1);
    }
    __syncthreads();

    // fragment address precompute (swizzled 256B rows)
    const int q = lane >> 3, r = lane & 7;
    uint32_t abase[2], ax[2];
    const uint32_t aq = (q & 2) ? 1u : 0u;
#pragma unroll
    for (int mi = 0; mi < 2; mi++) {
        int rowA = wm * 32 + mi * 16 + r + ((q & 1) ? 8 : 0);
        abase[mi] = (uint32_t)(rowA * 256);
        ax[mi] = (uint32_t)(rowA & 7);
    }
    uint32_t bbase[2], bx[2];
    const uint32_t bq = (q & 1) ? 1u : 0u;
#pragma unroll
    for (int j = 0; j < 2; j++) {
        int rowB = wn * 32 + j * 16 + r + ((q & 2) ? 8 : 0);
        bbase[j] = (uint32_t)(A_BYTES + rowB * 256);
        bx[j] = (uint32_t)(rowB & 7);
    }

#pragma unroll
    for (int mi = 0; mi < 2; mi++)
#pragma unroll
        for (int nj = 0; nj < 4; nj++)
#pragma unroll
            for (int c = 0; c < 4; c++) acc[mi][nj][c] = 0.0f;

    // prologue: issue k-tiles 0,1
    if (tid == 0) {
#pragma unroll
        for (int kt = 0; kt < 2; kt++) {
            uint32_t mb = bar + kt * 8;
            uint32_t st = sb + kt * STAGE_BYTES;
            MBARRIER_EXPECT_TX(mb, STAGE_BYTES);
            bulk_g2s(st,           A  + (size_t)kt * SLAB + (size_t)m0 * 128, A_BYTES, mb);
            bulk_g2s(st + A_BYTES, Bt + (size_t)kt * SLAB + (size_t)n0 * 128, B_BYTES, mb);
        }
    }

    for (int kt = 0; kt < KTILES; kt++) {
        const int s = kt % 3;
        MBARRIER_WAIT_PARITY(bar + s * 8, (kt / 3) & 1);
        const uint32_t st = sb + (uint32_t)s * STAGE_BYTES;

#pragma unroll
        for (int kk = 0; kk < 8; kk++) {
            uint32_t af[2][4], b01[4], b23[4];
            const uint32_t ac = 2 * kk + aq;
            const uint32_t bc = 2 * kk + bq;
            ldsm4(af[0], st + abase[0] + (((ac ^ ax[0]) << 4)));
            ldsm4(af[1], st + abase[1] + (((ac ^ ax[1]) << 4)));
            ldsm4(b01,   st + bbase[0] + (((bc ^ bx[0]) << 4)));
            ldsm4(b23,   st + bbase[1] + (((bc ^ bx[1]) << 4)));
#pragma unroll
            for (int mi = 0; mi < 2; mi++) {
                mma16(acc[mi][0], af[mi], b01[0], b01[1]);
                mma16(acc[mi][1], af[mi], b01[2], b01[3]);
                mma16(acc[mi][2], af[mi], b23[0], b23[1]);
                mma16(acc[mi][3], af[mi], b23[2], b23[3]);
            }
        }
        __syncthreads();                      // all warps done reading stage s
        if (kt + 2 < KTILES && tid == 0) {
            const int kn = kt + 2, sn = kn % 3;
            uint32_t mb = bar + sn * 8;
            uint32_t sd = sb + (uint32_t)sn * STAGE_BYTES;
            MBARRIER_EXPECT_TX(mb, STAGE_BYTES);
            bulk_g2s(sd,           A  + (size_t)kn * SLAB + (size_t)m0 * 128, A_BYTES, mb);
            bulk_g2s(sd + A_BYTES, Bt + (size_t)kn * SLAB + (size_t)n0 * 128, B_BYTES, mb);
        }
    }
}

// ---------------------------------------------------------------------------
// step1: ca1 = relu(drive_t * (1 + sigmoid(ec3 @ wec3ca1)) - ca1bias)
// ---------------------------------------------------------------------------
__global__ __launch_bounds__(256) void step1_mma(
    const float* __restrict__ ca1bias,
    float* __restrict__ ca1, float* __restrict__ c1h, int t, int last)
{
    extern __shared__ char smp[];
    float acc[2][4][4];
    gemm_mma_fp16(g_at1, g_wt1, smp, acc);

    const int lane = threadIdx.x & 31, warp = threadIdx.x >> 5;
    const int group = lane >> 2, tig = lane & 3;
    const int wm = warp & 3, wn = warp >> 2;
    const int m0 = blockIdx.y * 128, n0 = blockIdx.x * 64;
    const float* drive = &g_drive[t * NDIM];

#pragma unroll
    for (int mi = 0; mi < 2; mi++)
#pragma unroll
        for (int nj = 0; nj < 4; nj++)
#pragma unroll
            for (int c = 0; c < 4; c++) {
                const int m = m0 + wm * 32 + mi * 16 + group + ((c & 2) ? 8 : 0);
                const int n = n0 + wn * 32 + nj * 8 + tig * 2 + (c & 1);
                float v = fmaxf(drive[n] * (1.0f + sigmoidf(acc[mi][nj][c])) - ca1bias[n], 0.0f);
                if (last) ca1[m * NDIM + n] = v;
                g_at2[sw_idx(m, n)] = __float2half(v);
                if (m == 0) c1h[t * NDIM + n] = v;
            }
}

// ---------------------------------------------------------------------------
// step2: ec5 += ca1 @ wca1ec5; squash; ec3 *= ec5; cue @ t==10; threefry noise
// ---------------------------------------------------------------------------
__global__ __launch_bounds__(256) void step2_mma(
    const int* __restrict__ cue,
    float* __restrict__ ec3, float* __restrict__ ec5,
    float* __restrict__ e3h, float* __restrict__ e5h, int t)
{
    extern __shared__ char smp[];
    float acc[2][4][4];
    gemm_mma_fp16(g_at2, g_wt2, smp, acc);

    const int lane = threadIdx.x & 31, warp = threadIdx.x >> 5;
    const int group = lane >> 2, tig = lane & 3;
    const int wm = warp & 3, wn = warp >> 2;
    const int m0 = blockIdx.y * 128, n0 = blockIdx.x * 64;
    const uint32_t k0 = g_keys[2 * t], k1 = g_keys[2 * t + 1];
    const bool at_cue = (t == 10);

#pragma unroll
    for (int mi = 0; mi < 2; mi++)
#pragma unroll
        for (int nj = 0; nj < 4; nj++)
#pragma unroll
            for (int c = 0; c < 4; c++) {
                const int m = m0 + wm * 32 + mi * 16 + group + ((c & 2) ? 8 : 0);
                const int n = n0 + wn * 32 + nj * 8 + tig * 2 + (c & 1);
                const int gi = m * NDIM + n;
                float e5 = ec5[gi] + acc[mi][nj][c];       // 10*TS == 1.0 exactly
                e5 = 0.69f + 0.3f * sigmoidf(4.0f * (e5 - 0.3f));
                float e3 = e5 * ec3[gi];
                if (at_cue && (cue[gi] != 0)) e3 = 0.4f * e3 + 0.6f;
                if (noise_hit(k0, k1, (uint32_t)gi)) e3 = 0.5f * e3 + 0.3f;
                ec5[gi] = e5;
                ec3[gi] = e3;
                g_at1[sw_idx(m, n)] = __float2half(e3);
                if (m == 0) { e5h[t * NDIM + n] = e5; e3h[t * NDIM + n] = e3; }
            }
}

// ---------------------------------------------------------------------------
// act_cell = ca1 @ wca1act + actbias (tf32 operands, validated)
// ---------------------------------------------------------------------------
__global__ __launch_bounds__(128) void act_kernel(
    const float* __restrict__ ca1, const float* __restrict__ w,
    const float* __restrict__ bias, float* __restrict__ out)
{
    __shared__ float s0[128], s1[128];
    const int b = blockIdx.x;
    float a0 = 0.0f, a1 = 0.0f;
    for (int c = threadIdx.x; c < NDIM; c += 128) {
        float v = tf32r(ca1[b * NDIM + c]);
        a0 += v * tf32r(w[c * 2 + 0]);
        a1 += v * tf32r(w[c * 2 + 1]);
    }
    s0[threadIdx.x] = a0; s1[threadIdx.x] = a1;
    __syncthreads();
    for (int off = 64; off > 0; off >>= 1) {
        if (threadIdx.x < off) {
            s0[threadIdx.x] += s0[threadIdx.x + off];
            s1[threadIdx.x] += s1[threadIdx.x + off];
        }
        __syncthreads();
    }
    if (threadIdx.x == 0) {
        out[b * 2 + 0] = s0[0] + bias[0];
        out[b * 2 + 1] = s1[0] + bias[1];
    }
}

// ---------------------------------------------------------------------------
extern "C" void kernel_launch(void* const* d_in, const int* in_sizes, int n_in,
                              void* d_out, int out_size) {
    const int*   cue      = (const int*)d_in[0];     // bool -> int32 in harness
    const float* ec3_last = (const float*)d_in[1];
    const float* ec5_last = (const float*)d_in[2];
    const float* ca1_last = (const float*)d_in[3];
    const float* ca1bias  = (const float*)d_in[4];
    const float* wca3ca1  = (const float*)d_in[5];
    const float* wec3ca1  = (const float*)d_in[6];
    const float* wca1ec5  = (const float*)d_in[7];
    const float* wca1act  = (const float*)d_in[8];
    const float* actbias  = (const float*)d_in[9];
    (void)ca1_last;

    float* out = (float*)d_out;
    float* act = out + OFF_ACT;
    float* e3h = out + OFF_E3H;
    float* e5h = out + OFF_E5H;
    float* c1h = out + OFF_C1H;
    float* ec3 = out + OFF_EC3;
    float* ec5 = out + OFF_EC5;
    float* ca1 = out + OFF_CA1;

    cudaFuncSetAttribute(step1_mma, cudaFuncAttributeMaxDynamicSharedMemorySize, SMEM_DYN);
    cudaFuncSetAttribute(step2_mma, cudaFuncAttributeMaxDynamicSharedMemorySize, SMEM_DYN);

    prep_kernel<<<4197, 256>>>(wec3ca1, wca1ec5, ec3_last, ec5_last, wca3ca1, ec3, ec5);

    dim3 grid(NDIM / 64, BSZ / 128);       // 16 x 8 = 128 CTAs
    for (int t = 0; t < TLEN; t++) {
        step1_mma<<<grid, 256, SMEM_DYN>>>(ca1bias, ca1, c1h, t, t == TLEN - 1);
        step2_mma<<<grid, 256, SMEM_DYN>>>(cue, ec3, ec5, e3h, e5h, t);
    }
    act_kernel<<<BSZ, 128>>>(ca1, wca1act, actbias, act);
}